// round 2
// baseline (speedup 1.0000x reference)
#include <cuda_runtime.h>
#include <cuda_bf16.h>
#include <math_constants.h>

// Problem constants
#define Bc     32          // batch
#define Nn     1024        // tokens
#define INP    256
#define Hh     8           // heads
#define Dd     32          // dim_head
#define INNER  256         // H*D
#define OUP    256
#define QKVC   768         // 3*INNER

// ---------------------------------------------------------------------------
// Scratch (static device globals: allocation-free rule)
// ---------------------------------------------------------------------------
__device__ float g_q[Bc * Hh * Nn * Dd];     // [b,h,n,d]
__device__ float g_k[Bc * Hh * Nn * Dd];
__device__ float g_v[Bc * Hh * Nn * Dd];
__device__ float g_attn[Bc * Nn * INNER];    // [b,n,h*d]

// ---------------------------------------------------------------------------
// Kernel 1: qkv = x @ W_qkv, scattered into per-head [b,h,n,d] layout
//   x: [32768, 256], W_qkv: [256, 768]
//   64x64 tile per block, 256 threads, 4x4 micro-tile per thread, BK=16
// ---------------------------------------------------------------------------
__global__ void __launch_bounds__(256) qkv_gemm_kernel(
    const float* __restrict__ X, const float* __restrict__ W)
{
    __shared__ float As[16][64];   // As[k][m] (transposed for conflict-free reads)
    __shared__ float Bs[16][64];

    const int m0 = blockIdx.x * 64;
    const int n0 = blockIdx.y * 64;
    const int tid = threadIdx.x;
    const int tx = tid & 15;
    const int ty = tid >> 4;

    float acc[4][4] = {};

    for (int k0 = 0; k0 < INP; k0 += 16) {
        // load A tile (64 rows x 16 k) as float4 per thread
        {
            const int m  = tid >> 2;
            const int kk = (tid & 3) * 4;
            float4 a = *(const float4*)&X[(size_t)(m0 + m) * INP + k0 + kk];
            As[kk + 0][m] = a.x; As[kk + 1][m] = a.y;
            As[kk + 2][m] = a.z; As[kk + 3][m] = a.w;
        }
        // load B tile (16 k x 64 cols)
        {
            const int kb = tid >> 4;
            const int nn = (tid & 15) * 4;
            *(float4*)&Bs[kb][nn] =
                *(const float4*)&W[(size_t)(k0 + kb) * QKVC + n0 + nn];
        }
        __syncthreads();

        #pragma unroll
        for (int kk = 0; kk < 16; kk++) {
            float4 a4 = *(float4*)&As[kk][ty * 4];
            float4 b4 = *(float4*)&Bs[kk][tx * 4];
            float av[4] = {a4.x, a4.y, a4.z, a4.w};
            float bv[4] = {b4.x, b4.y, b4.z, b4.w};
            #pragma unroll
            for (int i = 0; i < 4; i++)
                #pragma unroll
                for (int j = 0; j < 4; j++)
                    acc[i][j] = fmaf(av[i], bv[j], acc[i][j]);
        }
        __syncthreads();
    }

    // scatter: col c -> (which of q/k/v, head, dim). n0 is a multiple of 64 and
    // 256 % 64 == 0, so the whole tile maps to one of q/k/v.
    const int t = n0 >> 8;                 // 0=q 1=k 2=v
    float* dst = (t == 0) ? g_q : (t == 1) ? g_k : g_v;

    #pragma unroll
    for (int i = 0; i < 4; i++) {
        const int r = m0 + ty * 4 + i;
        const int b = r >> 10;
        const int n = r & 1023;
        #pragma unroll
        for (int j = 0; j < 4; j++) {
            const int c  = n0 + tx * 4 + j;
            const int ci = c & 255;
            const int h  = ci >> 5;
            const int d  = ci & 31;
            dst[((((size_t)b * Hh + h) * Nn) + n) * Dd + d] = acc[i][j];
        }
    }
}

// ---------------------------------------------------------------------------
// Kernel 2: flash attention per (b, h, 64-row q tile) with relative-pos bias.
//   grid = (16, 8, 32); 256 threads.
//   Thread (ty,tx): S micro-tile rows ty*4..+3 x cols tx*4..+3,
//                   O accumulator rows ty*4..+3 x dims tx*2..+1.
// ---------------------------------------------------------------------------
__global__ void __launch_bounds__(256) attn_kernel(
    const float* __restrict__ bias_table, const int* __restrict__ rel_index)
{
    const int mt = blockIdx.x;    // q tile
    const int h  = blockIdx.y;
    const int b  = blockIdx.z;
    const int m0 = mt * 64;

    const size_t head_off = ((size_t)b * Hh + h) * Nn * Dd;
    const float* Qg = g_q + head_off;
    const float* Kg = g_k + head_off;
    const float* Vg = g_v + head_off;

    __shared__ float Qt[32][64];   // [d][row]
    __shared__ float Kt[32][64];   // [d][row]
    __shared__ float Vs[64][32];   // [row][d]
    __shared__ float Ps[64][68];   // probabilities, padded

    const int tid = threadIdx.x;
    const int tx = tid & 15;
    const int ty = tid >> 4;

    // Load Q tile transposed (2 float4 per thread)
    #pragma unroll
    for (int it = tid; it < 512; it += 256) {
        const int row = it >> 3;
        const int d4  = (it & 7) * 4;
        float4 q = *(const float4*)&Qg[(size_t)(m0 + row) * Dd + d4];
        Qt[d4 + 0][row] = q.x; Qt[d4 + 1][row] = q.y;
        Qt[d4 + 2][row] = q.z; Qt[d4 + 3][row] = q.w;
    }

    float m_i[4], l_i[4], Oacc[4][2];
    #pragma unroll
    for (int i = 0; i < 4; i++) {
        m_i[i] = -CUDART_INF_F;
        l_i[i] = 0.f;
        Oacc[i][0] = 0.f; Oacc[i][1] = 0.f;
    }
    const float scale = 0.1767766952966369f;   // 1/sqrt(32)

    for (int j0 = 0; j0 < Nn; j0 += 64) {
        __syncthreads();   // previous PV reads done before Kt/Vs/Ps reuse
        #pragma unroll
        for (int it = tid; it < 512; it += 256) {
            const int row = it >> 3;
            const int d4  = (it & 7) * 4;
            float4 k = *(const float4*)&Kg[(size_t)(j0 + row) * Dd + d4];
            Kt[d4 + 0][row] = k.x; Kt[d4 + 1][row] = k.y;
            Kt[d4 + 2][row] = k.z; Kt[d4 + 3][row] = k.w;
            *(float4*)&Vs[row][d4] =
                *(const float4*)&Vg[(size_t)(j0 + row) * Dd + d4];
        }
        __syncthreads();

        // S = Q K^T
        float S[4][4] = {};
        #pragma unroll
        for (int d = 0; d < 32; d++) {
            float4 q4 = *(float4*)&Qt[d][ty * 4];
            float4 k4 = *(float4*)&Kt[d][tx * 4];
            float qv[4] = {q4.x, q4.y, q4.z, q4.w};
            float kv[4] = {k4.x, k4.y, k4.z, k4.w};
            #pragma unroll
            for (int i = 0; i < 4; i++)
                #pragma unroll
                for (int j = 0; j < 4; j++)
                    S[i][j] = fmaf(qv[i], kv[j], S[i][j]);
        }

        // scale + relative-position bias gather
        #pragma unroll
        for (int i = 0; i < 4; i++) {
            const int gi = m0 + ty * 4 + i;
            const int* ri = &rel_index[(size_t)gi * Nn + j0 + tx * 4];
            #pragma unroll
            for (int j = 0; j < 4; j++) {
                const int idx = __ldg(&ri[j]);
                S[i][j] = fmaf(S[i][j], scale, __ldg(&bias_table[idx * Hh + h]));
            }
        }

        // online softmax (row reductions over the 16-lane tx group)
        #pragma unroll
        for (int i = 0; i < 4; i++) {
            float mx = fmaxf(fmaxf(S[i][0], S[i][1]), fmaxf(S[i][2], S[i][3]));
            #pragma unroll
            for (int off = 1; off < 16; off <<= 1)
                mx = fmaxf(mx, __shfl_xor_sync(0xffffffffu, mx, off));
            const float mnew = fmaxf(m_i[i], mx);
            const float corr = __expf(m_i[i] - mnew);
            float rs = 0.f;
            #pragma unroll
            for (int j = 0; j < 4; j++) {
                const float p = __expf(S[i][j] - mnew);
                S[i][j] = p;
                rs += p;
            }
            #pragma unroll
            for (int off = 1; off < 16; off <<= 1)
                rs += __shfl_xor_sync(0xffffffffu, rs, off);
            l_i[i] = l_i[i] * corr + rs;
            m_i[i] = mnew;
            Oacc[i][0] *= corr;
            Oacc[i][1] *= corr;
        }

        // stage P to shared for the PV product
        #pragma unroll
        for (int i = 0; i < 4; i++)
            #pragma unroll
            for (int j = 0; j < 4; j++)
                Ps[ty * 4 + i][tx * 4 + j] = S[i][j];
        __syncthreads();

        // O += P @ V   (thread owns rows ty*4..+3, dims tx*2..+1)
        #pragma unroll
        for (int j = 0; j < 64; j++) {
            const float v0 = Vs[j][tx * 2 + 0];
            const float v1 = Vs[j][tx * 2 + 1];
            #pragma unroll
            for (int i = 0; i < 4; i++) {
                const float p = Ps[ty * 4 + i][j];
                Oacc[i][0] = fmaf(p, v0, Oacc[i][0]);
                Oacc[i][1] = fmaf(p, v1, Oacc[i][1]);
            }
        }
    }

    // normalize and store in [b, n, h, d] layout
    #pragma unroll
    for (int i = 0; i < 4; i++) {
        const int gi = m0 + ty * 4 + i;
        const float inv = 1.f / l_i[i];
        const size_t base = (((size_t)b * Nn + gi) * Hh + h) * Dd + tx * 2;
        g_attn[base + 0] = Oacc[i][0] * inv;
        g_attn[base + 1] = Oacc[i][1] * inv;
    }
}

// ---------------------------------------------------------------------------
// Kernel 3: out = g_attn @ W_out + b_out   ([32768,256] @ [256,256])
// NOTE: g_attn referenced from device code (passing a __device__ symbol from
// host gives the host shadow address — that was the round-1 bug).
// ---------------------------------------------------------------------------
__global__ void __launch_bounds__(256) out_gemm_kernel(
    const float* __restrict__ W,
    const float* __restrict__ bias, float* __restrict__ out)
{
    __shared__ float As[16][64];
    __shared__ float Bs[16][64];

    const float* __restrict__ A = g_attn;

    const int m0 = blockIdx.x * 64;
    const int n0 = blockIdx.y * 64;
    const int tid = threadIdx.x;
    const int tx = tid & 15;
    const int ty = tid >> 4;

    float acc[4][4] = {};

    for (int k0 = 0; k0 < INNER; k0 += 16) {
        {
            const int m  = tid >> 2;
            const int kk = (tid & 3) * 4;
            float4 a = *(const float4*)&A[(size_t)(m0 + m) * INNER + k0 + kk];
            As[kk + 0][m] = a.x; As[kk + 1][m] = a.y;
            As[kk + 2][m] = a.z; As[kk + 3][m] = a.w;
        }
        {
            const int kb = tid >> 4;
            const int nn = (tid & 15) * 4;
            *(float4*)&Bs[kb][nn] =
                *(const float4*)&W[(size_t)(k0 + kb) * OUP + n0 + nn];
        }
        __syncthreads();

        #pragma unroll
        for (int kk = 0; kk < 16; kk++) {
            float4 a4 = *(float4*)&As[kk][ty * 4];
            float4 b4 = *(float4*)&Bs[kk][tx * 4];
            float av[4] = {a4.x, a4.y, a4.z, a4.w};
            float bv[4] = {b4.x, b4.y, b4.z, b4.w};
            #pragma unroll
            for (int i = 0; i < 4; i++)
                #pragma unroll
                for (int j = 0; j < 4; j++)
                    acc[i][j] = fmaf(av[i], bv[j], acc[i][j]);
        }
        __syncthreads();
    }

    #pragma unroll
    for (int i = 0; i < 4; i++) {
        const int r = m0 + ty * 4 + i;
        #pragma unroll
        for (int j = 0; j < 4; j++) {
            const int c = n0 + tx * 4 + j;
            out[(size_t)r * OUP + c] = acc[i][j] + bias[c];
        }
    }
}

// ---------------------------------------------------------------------------
// Launch
// ---------------------------------------------------------------------------
extern "C" void kernel_launch(void* const* d_in, const int* in_sizes, int n_in,
                              void* d_out, int out_size)
{
    const float* x          = (const float*)d_in[0];
    const float* W_qkv      = (const float*)d_in[1];
    const float* bias_table = (const float*)d_in[2];
    const float* W_out      = (const float*)d_in[3];
    const float* b_out      = (const float*)d_in[4];
    const int*   rel_index  = (const int*)d_in[5];
    float* out = (float*)d_out;

    (void)in_sizes; (void)n_in; (void)out_size;

    {
        dim3 grid(Bc * Nn / 64, QKVC / 64);   // (512, 12)
        qkv_gemm_kernel<<<grid, 256>>>(x, W_qkv);
    }
    {
        dim3 grid(Nn / 64, Hh, Bc);           // (16, 8, 32)
        attn_kernel<<<grid, 256>>>(bias_table, rel_index);
    }
    {
        dim3 grid(Bc * Nn / 64, OUP / 64);    // (512, 4)
        out_gemm_kernel<<<grid, 256>>>(W_out, b_out, out);
    }
}

// round 3
// speedup vs baseline: 2.2703x; 2.2703x over previous
#include <cuda_runtime.h>
#include <cuda_bf16.h>
#include <cstdint>

#define Bc 32
#define Nn 1024
#define INP 256
#define Hh 8
#define Dd 32
#define INNER 256
#define OUP 256
#define QKVC 768
#define NTOK (Bc * Nn)          // 32768

// ---------------------------------------------------------------------------
// Device-global scratch (allocation-free rule)
// ---------------------------------------------------------------------------
__device__ __nv_bfloat16 g_xh[NTOK * INP],  g_xl[NTOK * INP];       // x hi/lo
__device__ __nv_bfloat16 g_wqh[QKVC * INP], g_wql[QKVC * INP];      // W_qkv^T [n][k]
__device__ __nv_bfloat16 g_woh[OUP * INNER], g_wol[OUP * INNER];    // W_out^T [n][k]
__device__ __nv_bfloat16 g_qh[Bc*Hh*Nn*Dd], g_ql[Bc*Hh*Nn*Dd];      // [b,h,n,d] (pre-scaled)
__device__ __nv_bfloat16 g_kh[Bc*Hh*Nn*Dd], g_kl[Bc*Hh*Nn*Dd];      // [b,h,n,d]
__device__ __nv_bfloat16 g_vth[Bc*Hh*Dd*Nn], g_vtl[Bc*Hh*Dd*Nn];    // [b,h,d,n] (transposed)
__device__ __nv_bfloat16 g_oh[NTOK * INNER], g_ol[NTOK * INNER];    // attn out hi/lo
__device__ __nv_bfloat16 g_bias[Hh * Nn * Nn];                      // [h][i][j]

// ---------------------------------------------------------------------------
// Helpers
// ---------------------------------------------------------------------------
__device__ __forceinline__ uint32_t packbf(float x, float y) {
    __nv_bfloat162 t = __floats2bfloat162_rn(x, y);
    return *reinterpret_cast<uint32_t*>(&t);
}
__device__ __forceinline__ float2 unpackbf(uint32_t u) {
    __nv_bfloat162 t = *reinterpret_cast<__nv_bfloat162*>(&u);
    return make_float2(__bfloat162float(t.x), __bfloat162float(t.y));
}
// D += A(bf16x2 x4) * B(bf16x2 x2), fp32 accumulate
__device__ __forceinline__ void mma4(float* c, const uint32_t* a, uint32_t b0, uint32_t b1) {
    asm volatile(
        "mma.sync.aligned.m16n8k16.row.col.f32.bf16.bf16.f32 "
        "{%0,%1,%2,%3}, {%4,%5,%6,%7}, {%8,%9}, {%0,%1,%2,%3};\n"
        : "+f"(c[0]), "+f"(c[1]), "+f"(c[2]), "+f"(c[3])
        : "r"(a[0]), "r"(a[1]), "r"(a[2]), "r"(a[3]), "r"(b0), "r"(b1));
}

// ---------------------------------------------------------------------------
// Prep kernels: fp32 -> bf16 hi/lo splits (+ transposes, + bias gather)
// ---------------------------------------------------------------------------
__global__ void __launch_bounds__(256) prep_x(const float* __restrict__ x) {
    size_t i = (size_t)blockIdx.x * 256 + threadIdx.x;     // over NTOK*INP/4
    float4 v = ((const float4*)x)[i];
    uint32_t h01 = packbf(v.x, v.y);
    uint32_t h23 = packbf(v.z, v.w);
    float2 a = unpackbf(h01), b = unpackbf(h23);
    uint32_t l01 = packbf(v.x - a.x, v.y - a.y);
    uint32_t l23 = packbf(v.z - b.x, v.w - b.y);
    ((uint2*)g_xh)[i] = make_uint2(h01, h23);
    ((uint2*)g_xl)[i] = make_uint2(l01, l23);
}

__global__ void __launch_bounds__(256) prep_wqkv(const float* __restrict__ w) {
    int i = blockIdx.x * 256 + threadIdx.x;    // < 256*768
    int k = i / QKVC, n = i % QKVC;
    float v = w[i];
    __nv_bfloat16 h = __float2bfloat16(v);
    __nv_bfloat16 l = __float2bfloat16(v - __bfloat162float(h));
    g_wqh[n * INP + k] = h;
    g_wql[n * INP + k] = l;
}

__global__ void __launch_bounds__(256) prep_wout(const float* __restrict__ w) {
    int i = blockIdx.x * 256 + threadIdx.x;    // < 256*256
    int k = i >> 8, n = i & 255;
    float v = w[i];
    __nv_bfloat16 h = __float2bfloat16(v);
    __nv_bfloat16 l = __float2bfloat16(v - __bfloat162float(h));
    g_woh[n * INNER + k] = h;
    g_wol[n * INNER + k] = l;
}

// Expand bias_table via rel_index into g_bias[h][i][j] (bf16)
__global__ void __launch_bounds__(256) prep_bias(
    const float* __restrict__ table, const int* __restrict__ rel_index)
{
    int t = blockIdx.x * 256 + threadIdx.x;    // < 1024*256
    int i = t >> 8;
    int j = (t & 255) * 4;
    int4 idx = *(const int4*)&rel_index[i * Nn + j];
    int id[4] = {idx.x, idx.y, idx.z, idx.w};
    float vals[4][8];
    #pragma unroll
    for (int jj = 0; jj < 4; jj++) {
        const float4* tp = (const float4*)(table + (size_t)id[jj] * 8);
        float4 a = tp[0], b = tp[1];
        vals[jj][0] = a.x; vals[jj][1] = a.y; vals[jj][2] = a.z; vals[jj][3] = a.w;
        vals[jj][4] = b.x; vals[jj][5] = b.y; vals[jj][6] = b.z; vals[jj][7] = b.w;
    }
    #pragma unroll
    for (int h = 0; h < 8; h++) {
        uint2 o;
        o.x = packbf(vals[0][h], vals[1][h]);
        o.y = packbf(vals[2][h], vals[3][h]);
        *(uint2*)&g_bias[((size_t)h * Nn + i) * Nn + j] = o;
    }
}

// ---------------------------------------------------------------------------
// Kernel 1: QKV GEMM (bf16x3 tensor cores)
//   C[32768,768] = Xh/Xl @ (W^T)h/l ; epilogue scatters to q/k/v hi/lo layouts
//   block: 128 thr (4 warps, 2x2), tile BM=128 BN=64 BK=32
// ---------------------------------------------------------------------------
__global__ void __launch_bounds__(128) qkv_gemm_tc() {
    __shared__ __nv_bfloat16 Ah[128][40], Al[128][40];
    __shared__ __nv_bfloat16 Bh[64][40],  Bl[64][40];

    const int m0 = blockIdx.x * 128;
    const int n0 = blockIdx.y * 64;
    const int tid = threadIdx.x;
    const int warp = tid >> 5, lane = tid & 31;
    const int g = lane >> 2, t = lane & 3;
    const int wy = warp >> 1, wx = warp & 1;

    float c[4][4][4];
    #pragma unroll
    for (int a = 0; a < 4; a++)
        #pragma unroll
        for (int b = 0; b < 4; b++)
            #pragma unroll
            for (int d = 0; d < 4; d++) c[a][b][d] = 0.f;

    for (int k0 = 0; k0 < INP; k0 += 32) {
        __syncthreads();
        {   // stage A: thread -> full row tid (32 elems = 4 uint4)
            const uint4* sh = (const uint4*)&g_xh[(size_t)(m0 + tid) * INP + k0];
            const uint4* sl = (const uint4*)&g_xl[(size_t)(m0 + tid) * INP + k0];
            uint4* dh = (uint4*)&Ah[tid][0];
            uint4* dl = (uint4*)&Al[tid][0];
            #pragma unroll
            for (int u = 0; u < 4; u++) { dh[u] = sh[u]; dl[u] = sl[u]; }
        }
        {   // stage B^T: row = tid&63, two uint4 halves per thread
            const int row = tid & 63;
            const int u = (tid >> 6) * 2;
            const uint4* sh = (const uint4*)&g_wqh[(size_t)(n0 + row) * INP + k0];
            const uint4* sl = (const uint4*)&g_wql[(size_t)(n0 + row) * INP + k0];
            uint4* dh = (uint4*)&Bh[row][0];
            uint4* dl = (uint4*)&Bl[row][0];
            dh[u] = sh[u]; dh[u + 1] = sh[u + 1];
            dl[u] = sl[u]; dl[u + 1] = sl[u + 1];
        }
        __syncthreads();

        #pragma unroll
        for (int kt = 0; kt < 2; kt++) {
            const int cb = kt * 16 + 2 * t;
            uint32_t ah[4][4], al[4][4];
            #pragma unroll
            for (int mi = 0; mi < 4; mi++) {
                const int r = wy * 64 + mi * 16;
                ah[mi][0] = *(const uint32_t*)&Ah[r + g][cb];
                ah[mi][1] = *(const uint32_t*)&Ah[r + g + 8][cb];
                ah[mi][2] = *(const uint32_t*)&Ah[r + g][cb + 8];
                ah[mi][3] = *(const uint32_t*)&Ah[r + g + 8][cb + 8];
                al[mi][0] = *(const uint32_t*)&Al[r + g][cb];
                al[mi][1] = *(const uint32_t*)&Al[r + g + 8][cb];
                al[mi][2] = *(const uint32_t*)&Al[r + g][cb + 8];
                al[mi][3] = *(const uint32_t*)&Al[r + g + 8][cb + 8];
            }
            #pragma unroll
            for (int ni = 0; ni < 4; ni++) {
                const int nr = wx * 32 + ni * 8 + g;
                uint32_t bh0 = *(const uint32_t*)&Bh[nr][cb];
                uint32_t bh1 = *(const uint32_t*)&Bh[nr][cb + 8];
                uint32_t bl0 = *(const uint32_t*)&Bl[nr][cb];
                uint32_t bl1 = *(const uint32_t*)&Bl[nr][cb + 8];
                #pragma unroll
                for (int mi = 0; mi < 4; mi++) {
                    mma4(c[mi][ni], ah[mi], bh0, bh1);
                    mma4(c[mi][ni], ah[mi], bl0, bl1);
                    mma4(c[mi][ni], al[mi], bh0, bh1);
                }
            }
        }
    }

    // epilogue: scatter to q (scaled) / k / v^T, hi/lo bf16
    const float scale = 0.1767766952966369f;   // 1/sqrt(32)
    const int tpart = n0 >> 8;                 // 0=q 1=k 2=v (BN=64 | 256)
    #pragma unroll
    for (int mi = 0; mi < 4; mi++) {
        #pragma unroll
        for (int ni = 0; ni < 4; ni++) {
            const int col = n0 + wx * 32 + ni * 8 + 2 * t;
            const int ci = col & 255;
            const int h = ci >> 5, d = ci & 31;
            #pragma unroll
            for (int half = 0; half < 2; half++) {
                const int r = m0 + wy * 64 + mi * 16 + g + half * 8;
                const int b = r >> 10, n = r & 1023;
                float v0 = c[mi][ni][half * 2 + 0];
                float v1 = c[mi][ni][half * 2 + 1];
                if (tpart == 0) { v0 *= scale; v1 *= scale; }
                uint32_t hi = packbf(v0, v1);
                float2 hf = unpackbf(hi);
                uint32_t lo = packbf(v0 - hf.x, v1 - hf.y);
                if (tpart == 2) {
                    const size_t tv = (((size_t)(b * Hh + h)) * Dd + d) * Nn + n;
                    __nv_bfloat162 hb = *reinterpret_cast<__nv_bfloat162*>(&hi);
                    __nv_bfloat162 lb = *reinterpret_cast<__nv_bfloat162*>(&lo);
                    g_vth[tv] = hb.x;  g_vth[tv + Nn] = hb.y;
                    g_vtl[tv] = lb.x;  g_vtl[tv + Nn] = lb.y;
                } else {
                    const size_t idx = (((size_t)(b * Hh + h)) * Nn + n) * Dd + d;
                    if (tpart == 0) {
                        *(uint32_t*)&g_qh[idx] = hi; *(uint32_t*)&g_ql[idx] = lo;
                    } else {
                        *(uint32_t*)&g_kh[idx] = hi; *(uint32_t*)&g_kl[idx] = lo;
                    }
                }
            }
        }
    }
}

// ---------------------------------------------------------------------------
// Kernel 2: flash attention, tensor cores, bf16x3.
//   grid (16 qtiles, 8 heads, 32 batch); 128 thr; warp w owns q rows 16w..16w+15
// ---------------------------------------------------------------------------
__global__ void __launch_bounds__(128) attn_tc() {
    __shared__ __nv_bfloat16 Qh[64][40], Ql[64][40];
    __shared__ __nv_bfloat16 Kh[64][40], Kl[64][40];
    __shared__ __nv_bfloat16 Vh[32][72], Vl[32][72];

    const int qt = blockIdx.x, h = blockIdx.y, b = blockIdx.z;
    const int m0 = qt * 64;
    const int tid = threadIdx.x, warp = tid >> 5, lane = tid & 31;
    const int g = lane >> 2, t = lane & 3;

    const size_t head = (size_t)(b * Hh + h);
    const size_t qoff = (head * Nn + m0) * Dd;
    const size_t kbase = head * Nn * Dd;
    const size_t vbase = head * Dd * Nn;
    const size_t bbase = ((size_t)h * Nn + (m0 + warp * 16)) * Nn;

    {   // stage Q
        const int row = tid & 63;
        const int u = (tid >> 6) * 2;
        const uint4* sh = (const uint4*)&g_qh[qoff + (size_t)row * Dd];
        const uint4* sl = (const uint4*)&g_ql[qoff + (size_t)row * Dd];
        uint4* dh = (uint4*)&Qh[row][0];
        uint4* dl = (uint4*)&Ql[row][0];
        dh[u] = sh[u]; dh[u + 1] = sh[u + 1];
        dl[u] = sl[u]; dl[u + 1] = sl[u + 1];
    }
    __syncthreads();

    uint32_t qfh[2][4], qfl[2][4];
    #pragma unroll
    for (int kt = 0; kt < 2; kt++) {
        const int r = warp * 16;
        const int cb = kt * 16 + 2 * t;
        qfh[kt][0] = *(const uint32_t*)&Qh[r + g][cb];
        qfh[kt][1] = *(const uint32_t*)&Qh[r + g + 8][cb];
        qfh[kt][2] = *(const uint32_t*)&Qh[r + g][cb + 8];
        qfh[kt][3] = *(const uint32_t*)&Qh[r + g + 8][cb + 8];
        qfl[kt][0] = *(const uint32_t*)&Ql[r + g][cb];
        qfl[kt][1] = *(const uint32_t*)&Ql[r + g + 8][cb];
        qfl[kt][2] = *(const uint32_t*)&Ql[r + g][cb + 8];
        qfl[kt][3] = *(const uint32_t*)&Ql[r + g + 8][cb + 8];
    }

    float o[4][4];
    #pragma unroll
    for (int a = 0; a < 4; a++)
        #pragma unroll
        for (int d = 0; d < 4; d++) o[a][d] = 0.f;
    float m0r = -1e30f, m1r = -1e30f, l0r = 0.f, l1r = 0.f;

    for (int j0 = 0; j0 < Nn; j0 += 64) {
        __syncthreads();
        {   // stage K tile
            const int row = tid & 63;
            const int u = (tid >> 6) * 2;
            const uint4* sh = (const uint4*)&g_kh[kbase + (size_t)(j0 + row) * Dd];
            const uint4* sl = (const uint4*)&g_kl[kbase + (size_t)(j0 + row) * Dd];
            uint4* dh = (uint4*)&Kh[row][0];
            uint4* dl = (uint4*)&Kl[row][0];
            dh[u] = sh[u]; dh[u + 1] = sh[u + 1];
            dl[u] = sl[u]; dl[u + 1] = sl[u + 1];
        }
        {   // stage V^T tile
            const int row = tid & 31;
            const int u = (tid >> 5) * 2;
            const uint4* sh = (const uint4*)&g_vth[vbase + (size_t)row * Nn + j0];
            const uint4* sl = (const uint4*)&g_vtl[vbase + (size_t)row * Nn + j0];
            uint4* dh = (uint4*)&Vh[row][0];
            uint4* dl = (uint4*)&Vl[row][0];
            dh[u] = sh[u]; dh[u + 1] = sh[u + 1];
            dl[u] = sl[u]; dl[u + 1] = sl[u + 1];
        }
        __syncthreads();

        // S = Q K^T (scale folded into Q)
        float sc[8][4];
        #pragma unroll
        for (int nt = 0; nt < 8; nt++)
            #pragma unroll
            for (int d = 0; d < 4; d++) sc[nt][d] = 0.f;

        #pragma unroll
        for (int kt = 0; kt < 2; kt++) {
            const int cb = kt * 16 + 2 * t;
            #pragma unroll
            for (int nt = 0; nt < 8; nt++) {
                const int nr = nt * 8 + g;
                uint32_t bh0 = *(const uint32_t*)&Kh[nr][cb];
                uint32_t bh1 = *(const uint32_t*)&Kh[nr][cb + 8];
                uint32_t bl0 = *(const uint32_t*)&Kl[nr][cb];
                uint32_t bl1 = *(const uint32_t*)&Kl[nr][cb + 8];
                mma4(sc[nt], qfh[kt], bh0, bh1);
                mma4(sc[nt], qfh[kt], bl0, bl1);
                mma4(sc[nt], qfl[kt], bh0, bh1);
            }
        }

        // + relative position bias
        #pragma unroll
        for (int nt = 0; nt < 8; nt++) {
            const int j = j0 + nt * 8 + 2 * t;
            uint32_t u0 = *(const uint32_t*)&g_bias[bbase + (size_t)g * Nn + j];
            uint32_t u1 = *(const uint32_t*)&g_bias[bbase + (size_t)(g + 8) * Nn + j];
            float2 b0 = unpackbf(u0), b1 = unpackbf(u1);
            sc[nt][0] += b0.x; sc[nt][1] += b0.y;
            sc[nt][2] += b1.x; sc[nt][3] += b1.y;
        }

        // online softmax (rows g and g+8 of this warp's 16)
        float mx0 = -1e30f, mx1 = -1e30f;
        #pragma unroll
        for (int nt = 0; nt < 8; nt++) {
            mx0 = fmaxf(mx0, fmaxf(sc[nt][0], sc[nt][1]));
            mx1 = fmaxf(mx1, fmaxf(sc[nt][2], sc[nt][3]));
        }
        mx0 = fmaxf(mx0, __shfl_xor_sync(0xffffffffu, mx0, 1));
        mx0 = fmaxf(mx0, __shfl_xor_sync(0xffffffffu, mx0, 2));
        mx1 = fmaxf(mx1, __shfl_xor_sync(0xffffffffu, mx1, 1));
        mx1 = fmaxf(mx1, __shfl_xor_sync(0xffffffffu, mx1, 2));
        const float mn0 = fmaxf(m0r, mx0), mn1 = fmaxf(m1r, mx1);
        const float corr0 = __expf(m0r - mn0), corr1 = __expf(m1r - mn1);
        float rs0 = 0.f, rs1 = 0.f;
        #pragma unroll
        for (int nt = 0; nt < 8; nt++) {
            sc[nt][0] = __expf(sc[nt][0] - mn0);
            sc[nt][1] = __expf(sc[nt][1] - mn0);
            sc[nt][2] = __expf(sc[nt][2] - mn1);
            sc[nt][3] = __expf(sc[nt][3] - mn1);
            rs0 += sc[nt][0] + sc[nt][1];
            rs1 += sc[nt][2] + sc[nt][3];
        }
        rs0 += __shfl_xor_sync(0xffffffffu, rs0, 1);
        rs0 += __shfl_xor_sync(0xffffffffu, rs0, 2);
        rs1 += __shfl_xor_sync(0xffffffffu, rs1, 1);
        rs1 += __shfl_xor_sync(0xffffffffu, rs1, 2);
        l0r = l0r * corr0 + rs0;
        l1r = l1r * corr1 + rs1;
        m0r = mn0; m1r = mn1;
        #pragma unroll
        for (int nv = 0; nv < 4; nv++) {
            o[nv][0] *= corr0; o[nv][1] *= corr0;
            o[nv][2] *= corr1; o[nv][3] *= corr1;
        }

        // O += P V (P from registers: C-frag pairs -> A-frag)
        #pragma unroll
        for (int kt2 = 0; kt2 < 4; kt2++) {
            const float* s0 = sc[2 * kt2];
            const float* s1 = sc[2 * kt2 + 1];
            uint32_t pah[4], pal[4];
            pah[0] = packbf(s0[0], s0[1]);
            pah[1] = packbf(s0[2], s0[3]);
            pah[2] = packbf(s1[0], s1[1]);
            pah[3] = packbf(s1[2], s1[3]);
            {
                float2 f0 = unpackbf(pah[0]), f1 = unpackbf(pah[1]);
                float2 f2 = unpackbf(pah[2]), f3 = unpackbf(pah[3]);
                pal[0] = packbf(s0[0] - f0.x, s0[1] - f0.y);
                pal[1] = packbf(s0[2] - f1.x, s0[3] - f1.y);
                pal[2] = packbf(s1[0] - f2.x, s1[1] - f2.y);
                pal[3] = packbf(s1[2] - f3.x, s1[3] - f3.y);
            }
            const int cb = kt2 * 16 + 2 * t;
            #pragma unroll
            for (int nv = 0; nv < 4; nv++) {
                const int nr = nv * 8 + g;
                uint32_t vh0 = *(const uint32_t*)&Vh[nr][cb];
                uint32_t vh1 = *(const uint32_t*)&Vh[nr][cb + 8];
                uint32_t vl0 = *(const uint32_t*)&Vl[nr][cb];
                uint32_t vl1 = *(const uint32_t*)&Vl[nr][cb + 8];
                mma4(o[nv], pah, vh0, vh1);
                mma4(o[nv], pah, vl0, vl1);
                mma4(o[nv], pal, vh0, vh1);
            }
        }
    }

    // epilogue: normalize, split hi/lo, store [b, n, h*32+d]
    const float inv0 = 1.f / l0r, inv1 = 1.f / l1r;
    #pragma unroll
    for (int nv = 0; nv < 4; nv++) {
        const int colb = h * 32 + nv * 8 + 2 * t;
        const int r0 = m0 + warp * 16 + g;
        float v0 = o[nv][0] * inv0, v1 = o[nv][1] * inv0;
        float w0 = o[nv][2] * inv1, w1 = o[nv][3] * inv1;
        uint32_t hiA = packbf(v0, v1); float2 ha = unpackbf(hiA);
        uint32_t loA = packbf(v0 - ha.x, v1 - ha.y);
        uint32_t hiB = packbf(w0, w1); float2 hb = unpackbf(hiB);
        uint32_t loB = packbf(w0 - hb.x, w1 - hb.y);
        const size_t i0 = ((size_t)b * Nn + r0) * INNER + colb;
        const size_t i1 = i0 + (size_t)8 * INNER;
        *(uint32_t*)&g_oh[i0] = hiA; *(uint32_t*)&g_ol[i0] = loA;
        *(uint32_t*)&g_oh[i1] = hiB; *(uint32_t*)&g_ol[i1] = loB;
    }
}

// ---------------------------------------------------------------------------
// Kernel 3: out-projection GEMM (bf16x3): out = O @ W_out + b_out (fp32 out)
// ---------------------------------------------------------------------------
__global__ void __launch_bounds__(128) out_gemm_tc(
    const float* __restrict__ bias, float* __restrict__ out)
{
    __shared__ __nv_bfloat16 Ah[128][40], Al[128][40];
    __shared__ __nv_bfloat16 Bh[64][40],  Bl[64][40];

    const int m0 = blockIdx.x * 128;
    const int n0 = blockIdx.y * 64;
    const int tid = threadIdx.x;
    const int warp = tid >> 5, lane = tid & 31;
    const int g = lane >> 2, t = lane & 3;
    const int wy = warp >> 1, wx = warp & 1;

    float c[4][4][4];
    #pragma unroll
    for (int a = 0; a < 4; a++)
        #pragma unroll
        for (int b = 0; b < 4; b++)
            #pragma unroll
            for (int d = 0; d < 4; d++) c[a][b][d] = 0.f;

    for (int k0 = 0; k0 < INNER; k0 += 32) {
        __syncthreads();
        {
            const uint4* sh = (const uint4*)&g_oh[(size_t)(m0 + tid) * INNER + k0];
            const uint4* sl = (const uint4*)&g_ol[(size_t)(m0 + tid) * INNER + k0];
            uint4* dh = (uint4*)&Ah[tid][0];
            uint4* dl = (uint4*)&Al[tid][0];
            #pragma unroll
            for (int u = 0; u < 4; u++) { dh[u] = sh[u]; dl[u] = sl[u]; }
        }
        {
            const int row = tid & 63;
            const int u = (tid >> 6) * 2;
            const uint4* sh = (const uint4*)&g_woh[(size_t)(n0 + row) * INNER + k0];
            const uint4* sl = (const uint4*)&g_wol[(size_t)(n0 + row) * INNER + k0];
            uint4* dh = (uint4*)&Bh[row][0];
            uint4* dl = (uint4*)&Bl[row][0];
            dh[u] = sh[u]; dh[u + 1] = sh[u + 1];
            dl[u] = sl[u]; dl[u + 1] = sl[u + 1];
        }
        __syncthreads();

        #pragma unroll
        for (int kt = 0; kt < 2; kt++) {
            const int cb = kt * 16 + 2 * t;
            uint32_t ah[4][4], al[4][4];
            #pragma unroll
            for (int mi = 0; mi < 4; mi++) {
                const int r = wy * 64 + mi * 16;
                ah[mi][0] = *(const uint32_t*)&Ah[r + g][cb];
                ah[mi][1] = *(const uint32_t*)&Ah[r + g + 8][cb];
                ah[mi][2] = *(const uint32_t*)&Ah[r + g][cb + 8];
                ah[mi][3] = *(const uint32_t*)&Ah[r + g + 8][cb + 8];
                al[mi][0] = *(const uint32_t*)&Al[r + g][cb];
                al[mi][1] = *(const uint32_t*)&Al[r + g + 8][cb];
                al[mi][2] = *(const uint32_t*)&Al[r + g][cb + 8];
                al[mi][3] = *(const uint32_t*)&Al[r + g + 8][cb + 8];
            }
            #pragma unroll
            for (int ni = 0; ni < 4; ni++) {
                const int nr = wx * 32 + ni * 8 + g;
                uint32_t bh0 = *(const uint32_t*)&Bh[nr][cb];
                uint32_t bh1 = *(const uint32_t*)&Bh[nr][cb + 8];
                uint32_t bl0 = *(const uint32_t*)&Bl[nr][cb];
                uint32_t bl1 = *(const uint32_t*)&Bl[nr][cb + 8];
                #pragma unroll
                for (int mi = 0; mi < 4; mi++) {
                    mma4(c[mi][ni], ah[mi], bh0, bh1);
                    mma4(c[mi][ni], ah[mi], bl0, bl1);
                    mma4(c[mi][ni], al[mi], bh0, bh1);
                }
            }
        }
    }

    #pragma unroll
    for (int mi = 0; mi < 4; mi++) {
        #pragma unroll
        for (int ni = 0; ni < 4; ni++) {
            const int col = n0 + wx * 32 + ni * 8 + 2 * t;
            const float b0 = bias[col], b1 = bias[col + 1];
            #pragma unroll
            for (int half = 0; half < 2; half++) {
                const int r = m0 + wy * 64 + mi * 16 + g + half * 8;
                float2 v = make_float2(c[mi][ni][half * 2 + 0] + b0,
                                       c[mi][ni][half * 2 + 1] + b1);
                *(float2*)&out[(size_t)r * OUP + col] = v;
            }
        }
    }
}

// ---------------------------------------------------------------------------
// Launch
// ---------------------------------------------------------------------------
extern "C" void kernel_launch(void* const* d_in, const int* in_sizes, int n_in,
                              void* d_out, int out_size)
{
    const float* x          = (const float*)d_in[0];
    const float* W_qkv      = (const float*)d_in[1];
    const float* bias_table = (const float*)d_in[2];
    const float* W_out      = (const float*)d_in[3];
    const float* b_out      = (const float*)d_in[4];
    const int*   rel_index  = (const int*)d_in[5];
    float* out = (float*)d_out;
    (void)in_sizes; (void)n_in; (void)out_size;

    prep_x<<<NTOK * INP / 4 / 256, 256>>>(x);                 // 8192 blocks
    prep_wqkv<<<INP * QKVC / 256, 256>>>(W_qkv);              // 768
    prep_wout<<<INNER * OUP / 256, 256>>>(W_out);             // 256
    prep_bias<<<Nn * 256 / 256, 256>>>(bias_table, rel_index);// 1024

    qkv_gemm_tc<<<dim3(NTOK / 128, QKVC / 64), 128>>>();      // (256,12)
    attn_tc<<<dim3(Nn / 64, Hh, Bc), 128>>>();                // (16,8,32)
    out_gemm_tc<<<dim3(NTOK / 128, OUP / 64), 128>>>(b_out, out); // (256,4)
}

// round 4
// speedup vs baseline: 3.7881x; 1.6685x over previous
#include <cuda_runtime.h>
#include <cuda_bf16.h>
#include <cstdint>

#define Bc 32
#define Nn 1024
#define INP 256
#define Hh 8
#define Dd 32
#define INNER 256
#define OUP 256
#define QKVC 768
#define NTOK (Bc * Nn)

#define LOG2E 1.4426950408889634f

// ---------------------------------------------------------------------------
// Device-global scratch
// ---------------------------------------------------------------------------
__device__ __nv_bfloat16 g_xh[NTOK * INP],  g_xl[NTOK * INP];
__device__ __nv_bfloat16 g_wqh[QKVC * INP], g_wql[QKVC * INP];      // W_qkv^T [n][k]
__device__ __nv_bfloat16 g_woh[OUP * INNER], g_wol[OUP * INNER];    // W_out^T [n][k]
__device__ __nv_bfloat16 g_qh[Bc*Hh*Nn*Dd], g_ql[Bc*Hh*Nn*Dd];      // [b,h,n,d] *scale*log2e
__device__ __nv_bfloat16 g_kh[Bc*Hh*Nn*Dd], g_kl[Bc*Hh*Nn*Dd];
__device__ __nv_bfloat16 g_vth[Bc*Hh*Dd*Nn], g_vtl[Bc*Hh*Dd*Nn];    // [b,h,d,n]
__device__ __nv_bfloat16 g_oh[NTOK * INNER], g_ol[NTOK * INNER];
__device__ __nv_bfloat16 g_bias[Hh * Nn * Nn];                      // [h][i][j] * log2e

// ---------------------------------------------------------------------------
// Helpers
// ---------------------------------------------------------------------------
__device__ __forceinline__ uint32_t packbf(float x, float y) {
    __nv_bfloat162 t = __floats2bfloat162_rn(x, y);
    return *reinterpret_cast<uint32_t*>(&t);
}
__device__ __forceinline__ float2 unpackbf(uint32_t u) {
    __nv_bfloat162 t = *reinterpret_cast<__nv_bfloat162*>(&u);
    return make_float2(__bfloat162float(t.x), __bfloat162float(t.y));
}
__device__ __forceinline__ void mma4(float* c, const uint32_t* a, uint32_t b0, uint32_t b1) {
    asm volatile(
        "mma.sync.aligned.m16n8k16.row.col.f32.bf16.bf16.f32 "
        "{%0,%1,%2,%3}, {%4,%5,%6,%7}, {%8,%9}, {%0,%1,%2,%3};\n"
        : "+f"(c[0]), "+f"(c[1]), "+f"(c[2]), "+f"(c[3])
        : "r"(a[0]), "r"(a[1]), "r"(a[2]), "r"(a[3]), "r"(b0), "r"(b1));
}
__device__ __forceinline__ void ldsm4(uint32_t& r0, uint32_t& r1, uint32_t& r2,
                                      uint32_t& r3, const void* p) {
    uint32_t a = (uint32_t)__cvta_generic_to_shared(p);
    asm volatile("ldmatrix.sync.aligned.m8n8.x4.shared.b16 {%0,%1,%2,%3}, [%4];"
                 : "=r"(r0), "=r"(r1), "=r"(r2), "=r"(r3) : "r"(a));
}
__device__ __forceinline__ void cpa16(void* dst, const void* src) {
    uint32_t d = (uint32_t)__cvta_generic_to_shared(dst);
    asm volatile("cp.async.cg.shared.global [%0], [%1], 16;" :: "r"(d), "l"(src));
}
#define CP_COMMIT asm volatile("cp.async.commit_group;")
#define CP_WAIT0  asm volatile("cp.async.wait_group 0;")
__device__ __forceinline__ float ex2(float x) {
    float y; asm("ex2.approx.ftz.f32 %0, %1;" : "=f"(y) : "f"(x)); return y;
}

// ---------------------------------------------------------------------------
// Prep kernels
// ---------------------------------------------------------------------------
__global__ void __launch_bounds__(256) prep_x(const float* __restrict__ x) {
    size_t i = (size_t)blockIdx.x * 256 + threadIdx.x;
    float4 v = ((const float4*)x)[i];
    uint32_t h01 = packbf(v.x, v.y), h23 = packbf(v.z, v.w);
    float2 a = unpackbf(h01), b = unpackbf(h23);
    ((uint2*)g_xh)[i] = make_uint2(h01, h23);
    ((uint2*)g_xl)[i] = make_uint2(packbf(v.x - a.x, v.y - a.y),
                                   packbf(v.z - b.x, v.w - b.y));
}
__global__ void __launch_bounds__(256) prep_wqkv(const float* __restrict__ w) {
    int i = blockIdx.x * 256 + threadIdx.x;
    int k = i / QKVC, n = i % QKVC;
    float v = w[i];
    __nv_bfloat16 h = __float2bfloat16(v);
    g_wqh[n * INP + k] = h;
    g_wql[n * INP + k] = __float2bfloat16(v - __bfloat162float(h));
}
__global__ void __launch_bounds__(256) prep_wout(const float* __restrict__ w) {
    int i = blockIdx.x * 256 + threadIdx.x;
    int k = i >> 8, n = i & 255;
    float v = w[i];
    __nv_bfloat16 h = __float2bfloat16(v);
    g_woh[n * INNER + k] = h;
    g_wol[n * INNER + k] = __float2bfloat16(v - __bfloat162float(h));
}
__global__ void __launch_bounds__(256) prep_bias(
    const float* __restrict__ table, const int* __restrict__ rel_index)
{
    int tI = blockIdx.x * 256 + threadIdx.x;
    int i = tI >> 8;
    int j = (tI & 255) * 4;
    int4 idx = *(const int4*)&rel_index[i * Nn + j];
    int id[4] = {idx.x, idx.y, idx.z, idx.w};
    float vals[4][8];
    #pragma unroll
    for (int jj = 0; jj < 4; jj++) {
        const float4* tp = (const float4*)(table + (size_t)id[jj] * 8);
        float4 a = tp[0], b = tp[1];
        vals[jj][0] = a.x; vals[jj][1] = a.y; vals[jj][2] = a.z; vals[jj][3] = a.w;
        vals[jj][4] = b.x; vals[jj][5] = b.y; vals[jj][6] = b.z; vals[jj][7] = b.w;
    }
    #pragma unroll
    for (int h = 0; h < 8; h++) {
        uint2 o;
        o.x = packbf(vals[0][h] * LOG2E, vals[1][h] * LOG2E);
        o.y = packbf(vals[2][h] * LOG2E, vals[3][h] * LOG2E);
        *(uint2*)&g_bias[((size_t)h * Nn + i) * Nn + j] = o;
    }
}

// ---------------------------------------------------------------------------
// Kernel 1: QKV GEMM, BM=64 BN=64 BK=32, dbuf cp.async + ldmatrix, bf16x3
// ---------------------------------------------------------------------------
__global__ void __launch_bounds__(128) qkv_gemm_tc() {
    __shared__ __nv_bfloat16 Ah[2][64][40], Al[2][64][40];
    __shared__ __nv_bfloat16 Bh[2][64][40], Bl[2][64][40];

    const int m0 = blockIdx.x * 64;
    const int n0 = blockIdx.y * 64;
    const int tid = threadIdx.x;
    const int warp = tid >> 5, lane = tid & 31;
    const int g = lane >> 2, t = lane & 3;
    const int lsel = lane >> 3, lr = lane & 7;
    const int wy = warp >> 1, wx = warp & 1;

    auto issue = [&](int k0, int buf) {
        #pragma unroll
        for (int i = tid; i < 256; i += 128) {
            const int r = i >> 2, c = (i & 3) * 8;
            cpa16(&Ah[buf][r][c], &g_xh[(size_t)(m0 + r) * INP + k0 + c]);
            cpa16(&Al[buf][r][c], &g_xl[(size_t)(m0 + r) * INP + k0 + c]);
            cpa16(&Bh[buf][r][c], &g_wqh[(size_t)(n0 + r) * INP + k0 + c]);
            cpa16(&Bl[buf][r][c], &g_wql[(size_t)(n0 + r) * INP + k0 + c]);
        }
        CP_COMMIT;
    };

    float c4[2][4][4] = {};
    issue(0, 0);

    for (int kk = 0; kk < 8; kk++) {
        const int buf = kk & 1;
        CP_WAIT0;
        __syncthreads();
        if (kk < 7) issue((kk + 1) * 32, buf ^ 1);

        #pragma unroll
        for (int kt = 0; kt < 2; kt++) {
            uint32_t ah[2][4], al[2][4];
            #pragma unroll
            for (int mi = 0; mi < 2; mi++) {
                const int r = wy * 32 + mi * 16 + (lsel & 1) * 8 + lr;
                const int cc = kt * 16 + (lsel >> 1) * 8;
                ldsm4(ah[mi][0], ah[mi][1], ah[mi][2], ah[mi][3], &Ah[buf][r][cc]);
                ldsm4(al[mi][0], al[mi][1], al[mi][2], al[mi][3], &Al[buf][r][cc]);
            }
            #pragma unroll
            for (int ntp = 0; ntp < 2; ntp++) {
                const int r = wx * 32 + ntp * 16 + (lsel >> 1) * 8 + lr;
                const int cc = kt * 16 + (lsel & 1) * 8;
                uint32_t b0, b1, b2, b3, e0, e1, e2, e3;
                ldsm4(b0, b1, b2, b3, &Bh[buf][r][cc]);
                ldsm4(e0, e1, e2, e3, &Bl[buf][r][cc]);
                #pragma unroll
                for (int mi = 0; mi < 2; mi++) {
                    mma4(c4[mi][2*ntp],   ah[mi], b0, b1);
                    mma4(c4[mi][2*ntp],   ah[mi], e0, e1);
                    mma4(c4[mi][2*ntp],   al[mi], b0, b1);
                    mma4(c4[mi][2*ntp+1], ah[mi], b2, b3);
                    mma4(c4[mi][2*ntp+1], ah[mi], e2, e3);
                    mma4(c4[mi][2*ntp+1], al[mi], b2, b3);
                }
            }
        }
    }

    const float qscale = 0.1767766952966369f * LOG2E;   // 1/sqrt(32) * log2(e)
    const int tpart = n0 >> 8;                          // 0=q 1=k 2=v
    #pragma unroll
    for (int mi = 0; mi < 2; mi++) {
        #pragma unroll
        for (int ni = 0; ni < 4; ni++) {
            const int col = n0 + wx * 32 + ni * 8 + 2 * t;
            const int ci = col & 255;
            const int h = ci >> 5, d = ci & 31;
            #pragma unroll
            for (int half = 0; half < 2; half++) {
                const int r = m0 + wy * 32 + mi * 16 + g + half * 8;
                const int b = r >> 10, n = r & 1023;
                float v0 = c4[mi][ni][half * 2 + 0];
                float v1 = c4[mi][ni][half * 2 + 1];
                if (tpart == 0) { v0 *= qscale; v1 *= qscale; }
                uint32_t hi = packbf(v0, v1);
                float2 hf = unpackbf(hi);
                uint32_t lo = packbf(v0 - hf.x, v1 - hf.y);
                if (tpart == 2) {
                    const size_t tv = (((size_t)(b * Hh + h)) * Dd + d) * Nn + n;
                    __nv_bfloat162 hb = *reinterpret_cast<__nv_bfloat162*>(&hi);
                    __nv_bfloat162 lb = *reinterpret_cast<__nv_bfloat162*>(&lo);
                    g_vth[tv] = hb.x;  g_vth[tv + Nn] = hb.y;
                    g_vtl[tv] = lb.x;  g_vtl[tv + Nn] = lb.y;
                } else {
                    const size_t idx = (((size_t)(b * Hh + h)) * Nn + n) * Dd + d;
                    if (tpart == 0) {
                        *(uint32_t*)&g_qh[idx] = hi; *(uint32_t*)&g_ql[idx] = lo;
                    } else {
                        *(uint32_t*)&g_kh[idx] = hi; *(uint32_t*)&g_kl[idx] = lo;
                    }
                }
            }
        }
    }
}

// ---------------------------------------------------------------------------
// Kernel 2: flash attention, no-max softmax (logits bounded), dbuf + ldmatrix
// ---------------------------------------------------------------------------
__global__ void __launch_bounds__(128) attn_tc() {
    // per-buf: Kh@0 [64][40] | Kl@5120 | Vh@10240 [32][72] | Vl@14848; stride 19456
    __shared__ __align__(16) char smr[2 * 19456];

    const int qt = blockIdx.x, h = blockIdx.y, b = blockIdx.z;
    const int m0 = qt * 64;
    const int tid = threadIdx.x, warp = tid >> 5, lane = tid & 31;
    const int g = lane >> 2, t = lane & 3;
    const int lsel = lane >> 3, lr = lane & 7;

    const size_t head = (size_t)(b * Hh + h);
    const size_t qoff = (head * Nn + m0) * Dd;
    const size_t kbase = head * Nn * Dd;
    const size_t vbase = head * Dd * Nn;
    const size_t bbase = ((size_t)h * Nn + (m0 + warp * 16)) * Nn;

    typedef __nv_bfloat16 (*row40)[40];
    typedef __nv_bfloat16 (*row72)[72];
    auto KH = [&](int buf) { return (row40)(smr + buf * 19456); };
    auto KL = [&](int buf) { return (row40)(smr + buf * 19456 + 5120); };
    auto VH = [&](int buf) { return (row72)(smr + buf * 19456 + 10240); };
    auto VL = [&](int buf) { return (row72)(smr + buf * 19456 + 14848); };
    // Q staging aliases buffer 1 (consumed into registers before buf1 is filled)
    row40 Qh = (row40)(smr + 19456);
    row40 Ql = (row40)(smr + 19456 + 5120);

    auto issue = [&](int j0, int buf) {
        row40 kh = KH(buf); row40 kl = KL(buf);
        row72 vh = VH(buf); row72 vl = VL(buf);
        #pragma unroll
        for (int i = tid; i < 256; i += 128) {
            const int r = i >> 2, c = (i & 3) * 8;
            cpa16(&kh[r][c], &g_kh[kbase + (size_t)(j0 + r) * Dd + c]);
            cpa16(&kl[r][c], &g_kl[kbase + (size_t)(j0 + r) * Dd + c]);
        }
        #pragma unroll
        for (int i = tid; i < 256; i += 128) {
            const int r = i >> 3, c = (i & 7) * 8;
            cpa16(&vh[r][c], &g_vth[vbase + (size_t)r * Nn + j0 + c]);
            cpa16(&vl[r][c], &g_vtl[vbase + (size_t)r * Nn + j0 + c]);
        }
        CP_COMMIT;
    };

    issue(0, 0);

    {   // stage Q into alias region
        const int row = tid & 63;
        const int u = (tid >> 6) * 2;
        const uint4* sh = (const uint4*)&g_qh[qoff + (size_t)row * Dd];
        const uint4* sl = (const uint4*)&g_ql[qoff + (size_t)row * Dd];
        ((uint4*)&Qh[row][0])[u]     = sh[u];
        ((uint4*)&Qh[row][0])[u + 1] = sh[u + 1];
        ((uint4*)&Ql[row][0])[u]     = sl[u];
        ((uint4*)&Ql[row][0])[u + 1] = sl[u + 1];
    }
    __syncthreads();

    uint32_t qfh[2][4], qfl[2][4];
    #pragma unroll
    for (int kt = 0; kt < 2; kt++) {
        const int r = warp * 16 + (lsel & 1) * 8 + lr;
        const int cc = kt * 16 + (lsel >> 1) * 8;
        ldsm4(qfh[kt][0], qfh[kt][1], qfh[kt][2], qfh[kt][3], &Qh[r][cc]);
        ldsm4(qfl[kt][0], qfl[kt][1], qfl[kt][2], qfl[kt][3], &Ql[r][cc]);
    }

    float o[4][4] = {};
    float l0 = 0.f, l1 = 0.f;

    for (int jt = 0; jt < 16; jt++) {
        const int buf = jt & 1;
        CP_WAIT0;
        __syncthreads();   // also orders qf loads before issue into buf1
        if (jt < 15) issue((jt + 1) * 64, buf ^ 1);

        row40 kh = KH(buf); row40 kl = KL(buf);
        row72 vh = VH(buf); row72 vl = VL(buf);

        float sc[8][4];
        #pragma unroll
        for (int nt = 0; nt < 8; nt++)
            sc[nt][0] = sc[nt][1] = sc[nt][2] = sc[nt][3] = 0.f;

        #pragma unroll
        for (int kt = 0; kt < 2; kt++) {
            const int cc = kt * 16 + (lsel & 1) * 8;
            #pragma unroll
            for (int ntp = 0; ntp < 4; ntp++) {
                const int r = ntp * 16 + (lsel >> 1) * 8 + lr;
                uint32_t h0, h1, h2, h3, e0, e1, e2, e3;
                ldsm4(h0, h1, h2, h3, &kh[r][cc]);
                ldsm4(e0, e1, e2, e3, &kl[r][cc]);
                mma4(sc[2*ntp],   qfh[kt], h0, h1);
                mma4(sc[2*ntp],   qfh[kt], e0, e1);
                mma4(sc[2*ntp],   qfl[kt], h0, h1);
                mma4(sc[2*ntp+1], qfh[kt], h2, h3);
                mma4(sc[2*ntp+1], qfh[kt], e2, e3);
                mma4(sc[2*ntp+1], qfl[kt], h2, h3);
            }
        }

        // bias (pre-scaled by log2e) + exp2, accumulate row sums
        const int j0 = jt * 64;
        #pragma unroll
        for (int nt = 0; nt < 8; nt++) {
            const int j = j0 + nt * 8 + 2 * t;
            float2 b0v = unpackbf(*(const uint32_t*)&g_bias[bbase + (size_t)g * Nn + j]);
            float2 b1v = unpackbf(*(const uint32_t*)&g_bias[bbase + (size_t)(g + 8) * Nn + j]);
            sc[nt][0] = ex2(sc[nt][0] + b0v.x);
            sc[nt][1] = ex2(sc[nt][1] + b0v.y);
            sc[nt][2] = ex2(sc[nt][2] + b1v.x);
            sc[nt][3] = ex2(sc[nt][3] + b1v.y);
            l0 += sc[nt][0] + sc[nt][1];
            l1 += sc[nt][2] + sc[nt][3];
        }

        // O += P V (bf16x3, P from registers)
        #pragma unroll
        for (int kt2 = 0; kt2 < 4; kt2++) {
            const float* s0 = sc[2*kt2];
            const float* s1 = sc[2*kt2+1];
            uint32_t pah[4], pal[4];
            pah[0] = packbf(s0[0], s0[1]);
            pah[1] = packbf(s0[2], s0[3]);
            pah[2] = packbf(s1[0], s1[1]);
            pah[3] = packbf(s1[2], s1[3]);
            float2 f0 = unpackbf(pah[0]), f1 = unpackbf(pah[1]);
            float2 f2 = unpackbf(pah[2]), f3 = unpackbf(pah[3]);
            pal[0] = packbf(s0[0] - f0.x, s0[1] - f0.y);
            pal[1] = packbf(s0[2] - f1.x, s0[3] - f1.y);
            pal[2] = packbf(s1[0] - f2.x, s1[1] - f2.y);
            pal[3] = packbf(s1[2] - f3.x, s1[3] - f3.y);

            const int cc = kt2 * 16 + (lsel & 1) * 8;
            const int rA = (lsel >> 1) * 8 + lr;
            uint32_t v0, v1, v2, v3, w0, w1, w2, w3;
            ldsm4(v0, v1, v2, v3, &vh[rA][cc]);
            ldsm4(w0, w1, w2, w3, &vl[rA][cc]);
            mma4(o[0], pah, v0, v1); mma4(o[0], pah, w0, w1); mma4(o[0], pal, v0, v1);
            mma4(o[1], pah, v2, v3); mma4(o[1], pah, w2, w3); mma4(o[1], pal, v2, v3);
            ldsm4(v0, v1, v2, v3, &vh[16 + rA][cc]);
            ldsm4(w0, w1, w2, w3, &vl[16 + rA][cc]);
            mma4(o[2], pah, v0, v1); mma4(o[2], pah, w0, w1); mma4(o[2], pal, v0, v1);
            mma4(o[3], pah, v2, v3); mma4(o[3], pah, w2, w3); mma4(o[3], pal, v2, v3);
        }
    }

    // reduce l over the 4 lanes sharing a row, normalize, store hi/lo
    l0 += __shfl_xor_sync(0xffffffffu, l0, 1);
    l0 += __shfl_xor_sync(0xffffffffu, l0, 2);
    l1 += __shfl_xor_sync(0xffffffffu, l1, 1);
    l1 += __shfl_xor_sync(0xffffffffu, l1, 2);
    const float inv0 = 1.f / l0, inv1 = 1.f / l1;

    #pragma unroll
    for (int nv = 0; nv < 4; nv++) {
        const int colb = h * 32 + nv * 8 + 2 * t;
        const int r0 = m0 + warp * 16 + g;
        float v0 = o[nv][0] * inv0, v1 = o[nv][1] * inv0;
        float w0 = o[nv][2] * inv1, w1 = o[nv][3] * inv1;
        uint32_t hiA = packbf(v0, v1); float2 ha = unpackbf(hiA);
        uint32_t loA = packbf(v0 - ha.x, v1 - ha.y);
        uint32_t hiB = packbf(w0, w1); float2 hb = unpackbf(hiB);
        uint32_t loB = packbf(w0 - hb.x, w1 - hb.y);
        const size_t i0 = ((size_t)b * Nn + r0) * INNER + colb;
        const size_t i1 = i0 + (size_t)8 * INNER;
        *(uint32_t*)&g_oh[i0] = hiA; *(uint32_t*)&g_ol[i0] = loA;
        *(uint32_t*)&g_oh[i1] = hiB; *(uint32_t*)&g_ol[i1] = loB;
    }
}

// ---------------------------------------------------------------------------
// Kernel 3: out-projection GEMM (same scheme as kernel 1)
// ---------------------------------------------------------------------------
__global__ void __launch_bounds__(128) out_gemm_tc(
    const float* __restrict__ bias, float* __restrict__ out)
{
    __shared__ __nv_bfloat16 Ah[2][64][40], Al[2][64][40];
    __shared__ __nv_bfloat16 Bh[2][64][40], Bl[2][64][40];

    const int m0 = blockIdx.x * 64;
    const int n0 = blockIdx.y * 64;
    const int tid = threadIdx.x;
    const int warp = tid >> 5, lane = tid & 31;
    const int g = lane >> 2, t = lane & 3;
    const int lsel = lane >> 3, lr = lane & 7;
    const int wy = warp >> 1, wx = warp & 1;

    auto issue = [&](int k0, int buf) {
        #pragma unroll
        for (int i = tid; i < 256; i += 128) {
            const int r = i >> 2, c = (i & 3) * 8;
            cpa16(&Ah[buf][r][c], &g_oh[(size_t)(m0 + r) * INNER + k0 + c]);
            cpa16(&Al[buf][r][c], &g_ol[(size_t)(m0 + r) * INNER + k0 + c]);
            cpa16(&Bh[buf][r][c], &g_woh[(size_t)(n0 + r) * INNER + k0 + c]);
            cpa16(&Bl[buf][r][c], &g_wol[(size_t)(n0 + r) * INNER + k0 + c]);
        }
        CP_COMMIT;
    };

    float c4[2][4][4] = {};
    issue(0, 0);

    for (int kk = 0; kk < 8; kk++) {
        const int buf = kk & 1;
        CP_WAIT0;
        __syncthreads();
        if (kk < 7) issue((kk + 1) * 32, buf ^ 1);

        #pragma unroll
        for (int kt = 0; kt < 2; kt++) {
            uint32_t ah[2][4], al[2][4];
            #pragma unroll
            for (int mi = 0; mi < 2; mi++) {
                const int r = wy * 32 + mi * 16 + (lsel & 1) * 8 + lr;
                const int cc = kt * 16 + (lsel >> 1) * 8;
                ldsm4(ah[mi][0], ah[mi][1], ah[mi][2], ah[mi][3], &Ah[buf][r][cc]);
                ldsm4(al[mi][0], al[mi][1], al[mi][2], al[mi][3], &Al[buf][r][cc]);
            }
            #pragma unroll
            for (int ntp = 0; ntp < 2; ntp++) {
                const int r = wx * 32 + ntp * 16 + (lsel >> 1) * 8 + lr;
                const int cc = kt * 16 + (lsel & 1) * 8;
                uint32_t b0, b1, b2, b3, e0, e1, e2, e3;
                ldsm4(b0, b1, b2, b3, &Bh[buf][r][cc]);
                ldsm4(e0, e1, e2, e3, &Bl[buf][r][cc]);
                #pragma unroll
                for (int mi = 0; mi < 2; mi++) {
                    mma4(c4[mi][2*ntp],   ah[mi], b0, b1);
                    mma4(c4[mi][2*ntp],   ah[mi], e0, e1);
                    mma4(c4[mi][2*ntp],   al[mi], b0, b1);
                    mma4(c4[mi][2*ntp+1], ah[mi], b2, b3);
                    mma4(c4[mi][2*ntp+1], ah[mi], e2, e3);
                    mma4(c4[mi][2*ntp+1], al[mi], b2, b3);
                }
            }
        }
    }

    #pragma unroll
    for (int mi = 0; mi < 2; mi++) {
        #pragma unroll
        for (int ni = 0; ni < 4; ni++) {
            const int col = n0 + wx * 32 + ni * 8 + 2 * t;
            const float b0 = bias[col], b1 = bias[col + 1];
            #pragma unroll
            for (int half = 0; half < 2; half++) {
                const int r = m0 + wy * 32 + mi * 16 + g + half * 8;
                float2 v = make_float2(c4[mi][ni][half * 2 + 0] + b0,
                                       c4[mi][ni][half * 2 + 1] + b1);
                *(float2*)&out[(size_t)r * OUP + col] = v;
            }
        }
    }
}

// ---------------------------------------------------------------------------
// Launch
// ---------------------------------------------------------------------------
extern "C" void kernel_launch(void* const* d_in, const int* in_sizes, int n_in,
                              void* d_out, int out_size)
{
    const float* x          = (const float*)d_in[0];
    const float* W_qkv      = (const float*)d_in[1];
    const float* bias_table = (const float*)d_in[2];
    const float* W_out      = (const float*)d_in[3];
    const float* b_out      = (const float*)d_in[4];
    const int*   rel_index  = (const int*)d_in[5];
    float* out = (float*)d_out;
    (void)in_sizes; (void)n_in; (void)out_size;

    prep_x<<<NTOK * INP / 4 / 256, 256>>>(x);
    prep_wqkv<<<INP * QKVC / 256, 256>>>(W_qkv);
    prep_wout<<<INNER * OUP / 256, 256>>>(W_out);
    prep_bias<<<Nn * 256 / 256, 256>>>(bias_table, rel_index);

    qkv_gemm_tc<<<dim3(NTOK / 64, QKVC / 64), 128>>>();       // (512, 12)
    attn_tc<<<dim3(Nn / 64, Hh, Bc), 128>>>();                // (16, 8, 32)
    out_gemm_tc<<<dim3(NTOK / 64, OUP / 64), 128>>>(b_out, out); // (512, 4)
}